// round 11
// baseline (speedup 1.0000x reference)
#include <cuda_runtime.h>
#include <cuda_bf16.h>
#include <cstdint>
#include <stdint.h>

#define TT    1024
#define CC    256
#define E3    768
#define WINN  128
#define PADN  63
#define TPP   1150
#define LW    1023
#define SHIFTN 64
#define WPB   8
#define RB    136
#define GST   138
#define ZST   36
#define ATHREADS 512

// smem layout (bytes)
#define OFF_ZQ  37536          // Gm: 136*138 bf16 = 37536
#define OFF_ZK  57120          // Zq: 136*36*4 = 19584
#define OFF_F   76704          // Zk: 136*36*4 = 19584
#define SMEM_BYTES 84352

// Fs-region offsets (float slots)
#define F_US    0
#define F_WVS   136
#define F_INVA  272
#define F_HN    1296          // 130 used (+pad)
#define F_BQ    1428
#define F_BK    1492
#define F_C0    1556
#define F_HN2E  1560
#define F_HN2O  1624
#define F_WVB   1688          // 136 bf16 = 68 slots
#define F_HP2E  1756          // 73 u32
#define F_HP2O  1829          // 72 u32

// scale folded: 0.125 * log2(e)
#define SCC 0.18033688011112042f

__device__ float g_z[TT*E3];
__device__ float g_acc[2*TPP*CC];
__device__ float g_wti[CC*E3];
__device__ float g_wtM[CC*CC];      // (Wp@Wo) transposed: [c][e]
__device__ float g_obp[CC];         // Wp @ ob
__device__ float g_y[TT*CC];
__device__ float g_colsum[CC];
__device__ float g_segate[CC];

__device__ __forceinline__ float2 b2f(uint32_t u) {
    float2 r;
    r.x = __uint_as_float(u << 16);
    r.y = __uint_as_float(u & 0xffff0000u);
    return r;
}
__device__ __forceinline__ uint32_t f2b2(float a, float b) {
    __nv_bfloat162 t = __floats2bfloat162_rn(a, b);
    return *(uint32_t*)&t;
}
__device__ __forceinline__ float b2f1(__nv_bfloat16 h) {
    return __uint_as_float(((uint32_t)*(unsigned short*)&h) << 16);
}
__device__ __forceinline__ __nv_bfloat162 u2b(uint32_t u) {
    return *(__nv_bfloat162*)&u;
}

__device__ __forceinline__ float cntf(int t) {
    int tp = t + PADN;
    int lmin = tp - 127; if (lmin < 0) lmin = 0;
    int lmax = tp;       if (lmax > 1022) lmax = 1022;
    return (float)(lmax - lmin + 1);
}

// ---------------- init: zero accumulators + transpose Win ---------------
__global__ void k_init(const float* __restrict__ wi) {
    int i = blockIdx.x * 256 + threadIdx.x;
    if (i < 2*TPP*CC) g_acc[i] = 0.f;
    if (i < CC) g_colsum[i] = 0.f;
    if (i < E3*CC) {
        int e = i >> 8, c = i & 255;
        g_wti[c*E3 + e] = wi[i];
    }
}

// ---------------- fuse: M = Wp @ Wo (transposed), obp = Wp @ ob ----------
// 32 blocks x 8 e-rows: wp rows staged in smem, one wo sweep per block.
__global__ __launch_bounds__(256) void k_fuse(const float* __restrict__ wo,
                                              const float* __restrict__ wp,
                                              const float* __restrict__ ob) {
    __shared__ float wps[8][CC];
    int e0 = blockIdx.x * 8, tid = threadIdx.x;
#pragma unroll
    for (int r = 0; r < 8; r++)
        wps[r][tid] = wp[(e0 + r)*CC + tid];
    __syncthreads();

    float acc[8];
#pragma unroll
    for (int r = 0; r < 8; r++) acc[r] = 0.f;
#pragma unroll 4
    for (int k = 0; k < CC; k++) {
        float wov = wo[k*CC + tid];
#pragma unroll
        for (int r = 0; r < 8; r++) acc[r] += wps[r][k]*wov;
    }
#pragma unroll
    for (int r = 0; r < 8; r++)
        g_wtM[tid*CC + e0 + r] = acc[r];   // g_wtM[c][e] = M[e][c]

    int w = tid >> 5, lane = tid & 31;
    if (w < 8) {
        float s = 0.f;
#pragma unroll
        for (int j = 0; j < 8; j++) {
            int k = lane + 32*j;
            s += wps[w][k]*ob[k];
        }
#pragma unroll
        for (int o = 16; o; o >>= 1)
            s += __shfl_xor_sync(0xffffffffu, s, o);
        if (lane == 0) g_obp[e0 + w] = s;
    }
}

// ---------------- LayerNorm + z = LN(x) @ Win^T (8 rows, split-c) --------
__global__ __launch_bounds__(512) void k_ln_z(const float* __restrict__ x,
                                              const float* __restrict__ lg,
                                              const float* __restrict__ lb) {
    __shared__ float Y[8][CC];
    __shared__ float sA[8][8], sB[8][8];
    __shared__ float P[24][CC];
    int tid = threadIdx.x, half = tid >> 8, col = tid & 255;
    int warp = tid >> 5, lane = tid & 31;
    int w8 = warp & 7;
    int row0 = blockIdx.x * 8;

    float gv = lg[col], bv = lb[col];
    float xv[4];
#pragma unroll
    for (int r2 = 0; r2 < 4; r2++) {
        int r = 4*half + r2;
        float v = x[(row0 + r)*CC + col];
        xv[r2] = v;
        float s = v, s2 = v*v;
#pragma unroll
        for (int o = 16; o; o >>= 1) {
            s  += __shfl_xor_sync(0xffffffffu, s, o);
            s2 += __shfl_xor_sync(0xffffffffu, s2, o);
        }
        if (lane == 0) { sA[r][w8] = s; sB[r][w8] = s2; }
    }
    __syncthreads();
#pragma unroll
    for (int r2 = 0; r2 < 4; r2++) {
        int r = 4*half + r2;
        float s = 0.f, s2 = 0.f;
#pragma unroll
        for (int w2 = 0; w2 < 8; w2++) { s += sA[r][w2]; s2 += sB[r][w2]; }
        float mu  = s * (1.f/CC);
        float var = s2 * (1.f/CC) - mu*mu;
        float rstd = rsqrtf(var + 1e-5f);
        Y[r][col] = (xv[r2] - mu) * rstd * gv + bv;
    }
    __syncthreads();

    float acc[8][3];
#pragma unroll
    for (int r = 0; r < 8; r++)
#pragma unroll
        for (int j = 0; j < 3; j++) acc[r][j] = 0.f;

    int cbase = half * 128;
#pragma unroll 4
    for (int cc = 0; cc < 128; cc++) {
        int c = cbase + cc;
        float y8[8];
#pragma unroll
        for (int r = 0; r < 8; r++) y8[r] = Y[r][c];
#pragma unroll
        for (int j = 0; j < 3; j++) {
            float wv = g_wti[c*E3 + j*256 + col];
#pragma unroll
            for (int r = 0; r < 8; r++) acc[r][j] += y8[r]*wv;
        }
    }
    if (half) {
#pragma unroll
        for (int r = 0; r < 8; r++)
#pragma unroll
            for (int j = 0; j < 3; j++) P[r*3 + j][col] = acc[r][j];
    }
    __syncthreads();
    if (!half) {
#pragma unroll
        for (int r = 0; r < 8; r++)
#pragma unroll
            for (int j = 0; j < 3; j++)
                g_z[(row0 + r)*E3 + j*256 + col] = acc[r][j] + P[r*3 + j][col];
    }
}

// ---------------- windowed attention v6: shift-dedup (unchanged) ---------
__global__ __launch_bounds__(ATHREADS, 2) void k_attn(const float* __restrict__ inb) {
    extern __shared__ unsigned char smraw[];
    __nv_bfloat16* Gm = (__nv_bfloat16*)smraw;          // [136][138] bf16; later P
    uint32_t* Zq = (uint32_t*)(smraw + OFF_ZQ);         // [136][36] bf16x2
    uint32_t* Zk = (uint32_t*)(smraw + OFF_ZK);         // [136][36] bf16x2
    float* Fs   = (float*)(smraw + OFF_F);
    float* Us   = Fs + F_US;
    float* Wvs  = Fs + F_WVS;
    float* invA = Fs + F_INVA;
    float* Hn   = Fs + F_HN;      // [130] (128 + 2 zero pad)
    float* bqS  = Fs + F_BQ;
    float* bkS  = Fs + F_BK;
    float* c0S  = Fs + F_C0;
    uint32_t* Hn2e = (uint32_t*)(Fs + F_HN2E);
    uint32_t* Hn2o = (uint32_t*)(Fs + F_HN2O);
    __nv_bfloat16* Wvb = (__nv_bfloat16*)(Fs + F_WVB);
    uint32_t* HP2E = (uint32_t*)(Fs + F_HP2E);
    uint32_t* HP2O = (uint32_t*)(Fs + F_HP2O);
    uint32_t* Zv = Zq;            // alias (Zq dead after G phase)

    int tid = threadIdx.x;
    int bx = blockIdx.x, h = blockIdx.y;
    int v, g;
    if (bx < 128) { v = 0; g = bx; }
    else { int i = bx - 128; v = 1; g = (i < 16) ? i : i + 103; }
    bool dual = (v == 0) && (g >= 8) && (g < 111);
    int l0 = g * WPB;

    if (tid < 130)
        Hn[tid] = (tid < 128)
            ? 0.5f*(1.f - cosf(6.283185307179586f*(float)tid/127.f)) : 0.f;
    if (tid >= 192 && tid < 256) bqS[tid-192] = inb[h*64 + (tid-192)];
    if (tid >= 256 && tid < 320) bkS[tid-256] = inb[CC + h*64 + (tid-256)];

    for (int i = tid; i < RB*32; i += ATHREADS) {
        int r = i >> 5, jw = i & 31;
        int tp = l0 + r;
        float2 aq = make_float2(0.f, 0.f), ak = make_float2(0.f, 0.f);
        if (tp >= PADN && tp < PADN + TT) {
            int src = v ? ((tp - PADN - SHIFTN + TT) & (TT-1)) : (tp - PADN);
            const float* zp = &g_z[src*E3 + h*64 + 2*jw];
            aq = *(const float2*)zp;
            ak = *(const float2*)(zp + CC);
        }
        Zq[r*ZST + jw] = f2b2(aq.x, aq.y);
        Zk[r*ZST + jw] = f2b2(ak.x, ak.y);
    }
    __syncthreads();

    // ---- G (HFMA2, LDS.128, rows strided by 34 -> conflict-free) ----
    for (int idx = tid; idx < 34*34; idx += ATHREADS) {
        int ta = idx / 34, tb = idx - ta*34;
        __nv_bfloat162 acc2[4][4];
        __nv_bfloat162 z2 = __float2bfloat162_rn(0.f);
#pragma unroll
        for (int i = 0; i < 4; i++)
#pragma unroll
            for (int i2 = 0; i2 < 4; i2++) acc2[i][i2] = z2;
        for (int jw = 0; jw < 32; jw += 4) {
            uint4 A[4], B[4];
#pragma unroll
            for (int i = 0; i < 4; i++) {
                A[i] = *(const uint4*)&Zq[(ta + 34*i)*ZST + jw];
                B[i] = *(const uint4*)&Zk[(tb + 34*i)*ZST + jw];
            }
#pragma unroll
            for (int i = 0; i < 4; i++)
#pragma unroll
                for (int i2 = 0; i2 < 4; i2++) {
                    acc2[i][i2] = __hfma2(u2b(A[i].x), u2b(B[i2].x), acc2[i][i2]);
                    acc2[i][i2] = __hfma2(u2b(A[i].y), u2b(B[i2].y), acc2[i][i2]);
                    acc2[i][i2] = __hfma2(u2b(A[i].z), u2b(B[i2].z), acc2[i][i2]);
                    acc2[i][i2] = __hfma2(u2b(A[i].w), u2b(B[i2].w), acc2[i][i2]);
                }
        }
#pragma unroll
        for (int i = 0; i < 4; i++)
#pragma unroll
            for (int i2 = 0; i2 < 4; i2++) {
                float gf = SCC*(__low2float(acc2[i][i2]) + __high2float(acc2[i][i2]));
                Gm[(ta + 34*i)*GST + tb + 34*i2] = __float2bfloat16_rn(gf);
            }
    }
#define HPF(i) (((i) >= 8 && (i) < 136) ? Hn[(i)-8] : 0.f)
    if (tid < 136) {
        float su = 0.f;
        for (int jw = 0; jw < 32; jw++) {
            float2 q2 = b2f(Zq[tid*ZST + jw]);
            su += q2.x*bkS[2*jw] + q2.y*bkS[2*jw+1];
        }
        Us[tid] = SCC*su;
    } else if (tid < 272) {
        int r = tid - 136;
        float sw = 0.f;
        for (int jw = 0; jw < 32; jw++) {
            float2 k2 = b2f(Zk[r*ZST + jw]);
            sw += k2.x*bqS[2*jw] + k2.y*bqS[2*jw+1];
        }
        float wv = SCC*sw;
        Wvs[r] = wv;
        Wvb[r] = __float2bfloat16_rn(wv);
    } else if (tid == 272) {
        float c0 = 0.f;
        for (int j = 0; j < 64; j++) c0 += bqS[j]*bkS[j];
        c0S[0] = SCC*c0;
    } else if (tid >= 288 && tid < 352) {
        int j = tid - 288;
        Hn2e[j] = f2b2(Hn[2*j], Hn[2*j+1]);
    } else if (tid >= 352 && tid < 416) {
        int j = tid - 352;
        Hn2o[j] = f2b2(Hn[2*j+1], Hn[2*j+2]);
    } else if (tid >= 416) {
        for (int j = tid - 416; j < 73; j += 96)
            HP2E[j] = f2b2(HPF(2*j), HPF(2*j+1));
        for (int j = tid - 416; j < 72; j += 96)
            HP2O[j] = f2b2(HPF(2*j+1), HPF(2*j+2));
    }
    __syncthreads();

    // ---- load Zv (overwrites Zq) + pass A: softmax denominators ----
    for (int i = tid; i < RB*32; i += ATHREADS) {
        int r = i >> 5, jw = i & 31;
        int tp = l0 + r;
        float2 av = make_float2(0.f, 0.f);
        if (tp >= PADN && tp < PADN + TT) {
            int src = v ? ((tp - PADN - SHIFTN + TT) & (TT-1)) : (tp - PADN);
            av = *(const float2*)&g_z[src*E3 + 2*CC + h*64 + 2*jw];
        }
        Zv[r*ZST + jw] = f2b2(av.x, av.y);
    }
    float c0 = c0S[0];
    for (int rr = tid; rr < 1024; rr += ATHREADS) {
        int dl = rr >> 7, q = rr & 127;
        if (l0 + dl >= LW) continue;
        int a = dl + q;
        float hq = Hn[q];
        float base = fmaf(hq, Us[a], c0);
        __nv_bfloat162 hq2 = __float2bfloat162_rn(hq);
        __nv_bfloat162 base2 = __float2bfloat162_rn(base);
        int odd = dl & 1;
        int e0 = dl + odd;
        const uint32_t* gp = (const uint32_t*)(Gm + a*GST + e0);
        const uint32_t* wp = (const uint32_t*)Wvb + (e0 >> 1);
        const uint32_t* hp = odd ? Hn2o : Hn2e;
        int npairs = 64 - odd;
        float sum = odd ? 2.f*exp2f(base) : 0.f;
#pragma unroll 4
        for (int j = 0; j < npairs; j++) {
            __nv_bfloat162 s2 = __hfma2(
                __hfma2(hq2, u2b(gp[j]), u2b(wp[j])), u2b(hp[j]), base2);
            float2 sf = __bfloat1622float2(s2);
            sum += exp2f(sf.x) + exp2f(sf.y);
        }
        invA[dl*128 + q] = 1.f/sum;
    }
    __syncthreads();

    // ---- pass B: P[a][b] in place over G, 2-wide bf16x2 ----
    for (int a = tid >> 2; a < 136; a += 128) {
        uint32_t gq2[8], base2[8];
        float iv[8];
        float ua = Us[a];
#pragma unroll
        for (int dl = 0; dl < 8; dl++) {
            int qd = a - dl;
            bool va = (qd >= 0 && qd < 128);
            float hq = va ? Hn[qd] : 0.f;
            float bs = fmaf(hq, ua, c0);
            gq2[dl] = f2b2(hq, hq);
            base2[dl] = f2b2(bs, bs);
            iv[dl] = (va && (l0 + dl) < LW) ? invA[dl*128 + qd] : 0.f;
        }
        int q4 = tid & 3;
        for (int jj = 0; jj < 17; jj++) {
            int b2 = 2*q4 + 8*jj;
            uint32_t gval2 = *(const uint32_t*)&Gm[a*GST + b2];
            uint32_t wb2 = ((const uint32_t*)Wvb)[b2 >> 1];
            float p0 = 0.f, p1 = 0.f;
#pragma unroll
            for (int dl = 0; dl < 8; dl++) {
                uint32_t hk2u = (dl & 1)
                    ? HP2O[(b2 - dl + 7) >> 1]
                    : HP2E[(b2 - dl + 8) >> 1];
                __nv_bfloat162 s2 = __hfma2(
                    __hfma2(u2b(gq2[dl]), u2b(gval2), u2b(wb2)),
                    u2b(hk2u), u2b(base2[dl]));
                float2 sf = __bfloat1622float2(s2);
                float2 hk = b2f(hk2u);
                p0 = fmaf(hk.x*iv[dl], exp2f(sf.x), p0);
                p1 = fmaf(hk.y*iv[dl], exp2f(sf.y), p1);
            }
            *(uint32_t*)&Gm[a*GST + b2] = f2b2(p0, p1);
        }
    }
    __syncthreads();

    // ---- PV (HFMA2 + f32 flush, LDS.128 V loads) ----
    for (int idx = tid; idx < 68*8; idx += ATHREADS) {
        int ta = idx >> 3, tj = idx & 7;
        int a0 = ta*2, j0 = tj*8;
        float2 accf[2][4];
#pragma unroll
        for (int i = 0; i < 2; i++)
#pragma unroll
            for (int c = 0; c < 4; c++) accf[i][c] = make_float2(0.f, 0.f);
        __nv_bfloat162 z2 = __float2bfloat162_rn(0.f);
        for (int cb = 0; cb < 68; cb += 8) {
            int ce = (cb + 8 < 68) ? cb + 8 : 68;
            __nv_bfloat162 acc2[2][4];
#pragma unroll
            for (int i = 0; i < 2; i++)
#pragma unroll
                for (int c = 0; c < 4; c++) acc2[i][c] = z2;
            for (int bw = cb; bw < ce; bw++) {
                uint4 V0 = *(const uint4*)&Zv[(2*bw)*ZST + (j0 >> 1)];
                uint4 V1 = *(const uint4*)&Zv[(2*bw+1)*ZST + (j0 >> 1)];
#pragma unroll
                for (int i = 0; i < 2; i++) {
                    __nv_bfloat162 pp = u2b(*(const uint32_t*)&Gm[(a0+i)*GST + 2*bw]);
                    __nv_bfloat162 pl = __low2bfloat162(pp);
                    __nv_bfloat162 ph = __high2bfloat162(pp);
                    acc2[i][0] = __hfma2(pl, u2b(V0.x), acc2[i][0]);
                    acc2[i][1] = __hfma2(pl, u2b(V0.y), acc2[i][1]);
                    acc2[i][2] = __hfma2(pl, u2b(V0.z), acc2[i][2]);
                    acc2[i][3] = __hfma2(pl, u2b(V0.w), acc2[i][3]);
                    acc2[i][0] = __hfma2(ph, u2b(V1.x), acc2[i][0]);
                    acc2[i][1] = __hfma2(ph, u2b(V1.y), acc2[i][1]);
                    acc2[i][2] = __hfma2(ph, u2b(V1.z), acc2[i][2]);
                    acc2[i][3] = __hfma2(ph, u2b(V1.w), acc2[i][3]);
                }
            }
#pragma unroll
            for (int i = 0; i < 2; i++)
#pragma unroll
                for (int c = 0; c < 4; c++) {
                    float2 f = __bfloat1622float2(acc2[i][c]);
                    accf[i][c].x += f.x;
                    accf[i][c].y += f.y;
                }
        }
#pragma unroll
        for (int i = 0; i < 2; i++) {
            int tp = l0 + a0 + i;
            if (tp < TPP) {
                float* dst = &g_acc[((size_t)v*TPP + tp)*CC + h*64 + j0];
#pragma unroll
                for (int c = 0; c < 4; c++) {
                    atomicAdd(&dst[2*c],   accf[i][c].x);
                    atomicAdd(&dst[2*c+1], accf[i][c].y);
                }
                if (dual) {
                    float* dst2 = &g_acc[((size_t)TPP + tp + SHIFTN)*CC + h*64 + j0];
#pragma unroll
                    for (int c = 0; c < 4; c++) {
                        atomicAdd(&dst2[2*c],   accf[i][c].x);
                        atomicAdd(&dst2[2*c+1], accf[i][c].y);
                    }
                }
            }
        }
    }
}

// ---------------- finalize: fused GEMM, 4 rows, split-c 512 thr ----------
__global__ __launch_bounds__(512) void k_finalize(const float* __restrict__ inb,
                                                  const float* __restrict__ pb) {
    __shared__ float U[4][CC];
    __shared__ float P[4][CC];
    __shared__ float bb[4];
    int tid = threadIdx.x, half = tid >> 8, col = tid & 255;
    int t0 = blockIdx.x * 4;

    for (int idx = tid; idx < 4*CC; idx += 512) {
        int r = idx >> 8, c = idx & 255;
        float bvv = inb[2*CC + c];
        int t = t0 + r;
        float cm = cntf(t);
        float am = g_acc[(size_t)(t + PADN)*CC + c];
        float pm = (am + cm*bvv) / (cm + 1e-6f);
        int tau = (t + SHIFTN) & (TT-1);
        float cs = cntf(tau);
        float as = g_acc[(size_t)TPP*CC + (size_t)(tau + PADN)*CC + c];
        float ps = (as + cs*bvv) / (cs + 1e-6f);
        U[r][c] = 0.5f*(pm + ps);
    }
    if (tid < 4) {
        int t = t0 + tid;
        float cm = cntf(t);
        float cs = cntf((t + SHIFTN) & (TT-1));
        bb[tid] = 0.5f*(cm/(cm + 1e-6f) + cs/(cs + 1e-6f));
    }
    __syncthreads();

    float acc[4];
#pragma unroll
    for (int r = 0; r < 4; r++) acc[r] = 0.f;
    int cbase = half * 128;
#pragma unroll 8
    for (int cc = 0; cc < 128; cc++) {
        int c = cbase + cc;
        float w = g_wtM[c*CC + col];
#pragma unroll
        for (int r = 0; r < 4; r++) acc[r] += U[r][c]*w;
    }
    if (half) {
#pragma unroll
        for (int r = 0; r < 4; r++) P[r][col] = acc[r];
    }
    __syncthreads();
    if (!half) {
        float pbv = pb[col], obp = g_obp[col];
        float colpart = 0.f;
#pragma unroll
        for (int r = 0; r < 4; r++) {
            float yp = acc[r] + P[r][col] + bb[r]*obp + pbv;
            g_y[(size_t)(t0 + r)*CC + col] = yp;
            colpart += yp;
        }
        atomicAdd(&g_colsum[col], colpart);
    }
}

// ---------------- SE gate ----------------
__global__ __launch_bounds__(256) void k_se(const float* __restrict__ w1,
                                            const float* __restrict__ w2) {
    __shared__ float s[CC], s1[16];
    int tid = threadIdx.x;
    s[tid] = g_colsum[tid] * (1.f/(float)TT);
    __syncthreads();
    if (tid < 16) {
        float a = 0.f;
        for (int c = 0; c < CC; c++) a += s[c]*w1[tid*CC + c];
        s1[tid] = fmaxf(a, 0.f);
    }
    __syncthreads();
    float a = 0.f;
#pragma unroll
    for (int j = 0; j < 16; j++) a += s1[j]*w2[tid*16 + j];
    g_segate[tid] = 1.f/(1.f + __expf(-a));
}

// ---------------- residual + gate ----------------
__global__ void k_out(const float* __restrict__ x, float* __restrict__ out) {
    int i = blockIdx.x*256 + threadIdx.x;
    out[i] = x[i] + g_y[i]*g_segate[i & 255];
}

extern "C" void kernel_launch(void* const* d_in, const int* in_sizes, int n_in,
                              void* d_out, int out_size) {
    const float* x  = (const float*)d_in[0];
    const float* lg = (const float*)d_in[1];
    const float* lb = (const float*)d_in[2];
    const float* wi = (const float*)d_in[3];
    const float* ib = (const float*)d_in[4];
    const float* wo = (const float*)d_in[5];
    const float* ob = (const float*)d_in[6];
    const float* wp = (const float*)d_in[7];
    const float* pb = (const float*)d_in[8];
    const float* w1 = (const float*)d_in[9];
    const float* w2 = (const float*)d_in[10];
    float* out = (float*)d_out;

    cudaFuncSetAttribute(k_attn, cudaFuncAttributeMaxDynamicSharedMemorySize,
                         SMEM_BYTES);

    k_init<<<2300, 256>>>(wi);
    k_fuse<<<32, 256>>>(wo, wp, ob);
    k_ln_z<<<128, 512>>>(x, lg, lb);
    k_attn<<<dim3(153, 4), ATHREADS, SMEM_BYTES>>>(ib);
    k_finalize<<<256, 512>>>(ib, pb);
    k_se<<<1, 256>>>(w1, w2);
    k_out<<<1024, 256>>>(x, out);
}

// round 12
// speedup vs baseline: 1.3564x; 1.3564x over previous
#include <cuda_runtime.h>
#include <cuda_bf16.h>
#include <cstdint>
#include <stdint.h>

#define TT    1024
#define CC    256
#define E3    768
#define WINN  128
#define PADN  63
#define TPP   1150
#define LW    1023
#define SHIFTN 64
#define WPB   16
#define RBP   144          // padded rows (real 143)
#define GST   146
#define ZST   36
#define PST   144          // P row stride (bf16)
#define ATHREADS 512

// smem layout (bytes)
#define OFF_PZ  42048          // Gm: 144*146*2 = 42048; P aliases Zq/Zk region
#define OFF_ZK  62784          // Zk = OFF_PZ + 20736
#define OFF_F   83520
#define SMEM_BYTES 94784

// Fs-region offsets (float slots)
#define F_US    0
#define F_INVA  144           // [16][128]
#define F_HN    2192          // 132
#define F_BQ    2324
#define F_BK    2388
#define F_C0    2452
#define F_HN2E  2456
#define F_HN2O  2520
#define F_WVB   2584          // 144 bf16 = 72 u32
#define F_HP2E  2656          // 80 u32
#define F_HP2O  2736          // 80 u32

// scale folded: 0.125 * log2(e)
#define SCC 0.18033688011112042f

__device__ float g_z[TT*E3];
__device__ float g_acc[2*TPP*CC];
__device__ float g_wti[CC*E3];
__device__ float g_wto[CC*CC];
__device__ float g_wtp[CC*CC];
__device__ float g_y[TT*CC];
__device__ float g_colsum[CC];
__device__ float g_segate[CC];

__device__ __forceinline__ float2 b2f(uint32_t u) {
    float2 r;
    r.x = __uint_as_float(u << 16);
    r.y = __uint_as_float(u & 0xffff0000u);
    return r;
}
__device__ __forceinline__ uint32_t f2b2(float a, float b) {
    __nv_bfloat162 t = __floats2bfloat162_rn(a, b);
    return *(uint32_t*)&t;
}
__device__ __forceinline__ float b2f1(__nv_bfloat16 h) {
    return __uint_as_float(((uint32_t)*(unsigned short*)&h) << 16);
}
__device__ __forceinline__ __nv_bfloat162 u2b(uint32_t u) {
    return *(__nv_bfloat162*)&u;
}

__device__ __forceinline__ float cntf(int t) {
    int tp = t + PADN;
    int lmin = tp - 127; if (lmin < 0) lmin = 0;
    int lmax = tp;       if (lmax > 1022) lmax = 1022;
    return (float)(lmax - lmin + 1);
}

// ---------------- init: zero accumulators + transpose weights (R9) -------
__global__ void k_init(const float* __restrict__ wi,
                       const float* __restrict__ wo,
                       const float* __restrict__ wp) {
    int i = blockIdx.x * 256 + threadIdx.x;
    if (i < 2*TPP*CC) g_acc[i] = 0.f;
    if (i < CC) g_colsum[i] = 0.f;
    if (i < E3*CC) {
        int e = i >> 8, c = i & 255;
        g_wti[c*E3 + e] = wi[i];
    }
    if (i < CC*CC) {
        int e = i >> 8, c = i & 255;
        g_wto[c*CC + e] = wo[i];
        g_wtp[c*CC + e] = wp[i];
    }
}

// ---------------- LayerNorm + z (R9: 256 blocks, 4 rows, split-c) --------
__global__ __launch_bounds__(512) void k_ln_z(const float* __restrict__ x,
                                              const float* __restrict__ lg,
                                              const float* __restrict__ lb) {
    __shared__ float Y[4][CC];
    __shared__ float sA[4][8], sB[4][8];
    __shared__ float P[12][CC];
    int tid = threadIdx.x, half = tid >> 8, col = tid & 255;
    int warp = tid >> 5, lane = tid & 31;
    int w8 = warp & 7;
    int row0 = blockIdx.x * 4;

    float gv = lg[col], bv = lb[col];
    float xv[2];
#pragma unroll
    for (int r2 = 0; r2 < 2; r2++) {
        int r = 2*half + r2;
        float v = x[(row0 + r)*CC + col];
        xv[r2] = v;
        float s = v, s2 = v*v;
#pragma unroll
        for (int o = 16; o; o >>= 1) {
            s  += __shfl_xor_sync(0xffffffffu, s, o);
            s2 += __shfl_xor_sync(0xffffffffu, s2, o);
        }
        if (lane == 0) { sA[r][w8] = s; sB[r][w8] = s2; }
    }
    __syncthreads();
#pragma unroll
    for (int r2 = 0; r2 < 2; r2++) {
        int r = 2*half + r2;
        float s = 0.f, s2 = 0.f;
#pragma unroll
        for (int w2 = 0; w2 < 8; w2++) { s += sA[r][w2]; s2 += sB[r][w2]; }
        float mu  = s * (1.f/CC);
        float var = s2 * (1.f/CC) - mu*mu;
        float rstd = rsqrtf(var + 1e-5f);
        Y[r][col] = (xv[r2] - mu) * rstd * gv + bv;
    }
    __syncthreads();

    float acc[4][3];
#pragma unroll
    for (int r = 0; r < 4; r++)
#pragma unroll
        for (int j = 0; j < 3; j++) acc[r][j] = 0.f;

    int cbase = half * 128;
#pragma unroll 4
    for (int cc = 0; cc < 128; cc++) {
        int c = cbase + cc;
        float y4[4];
#pragma unroll
        for (int r = 0; r < 4; r++) y4[r] = Y[r][c];
#pragma unroll
        for (int j = 0; j < 3; j++) {
            float wv = g_wti[c*E3 + j*256 + col];
#pragma unroll
            for (int r = 0; r < 4; r++) acc[r][j] += y4[r]*wv;
        }
    }
    if (half) {
#pragma unroll
        for (int r = 0; r < 4; r++)
#pragma unroll
            for (int j = 0; j < 3; j++) P[r*3 + j][col] = acc[r][j];
    }
    __syncthreads();
    if (!half) {
#pragma unroll
        for (int r = 0; r < 4; r++)
#pragma unroll
            for (int j = 0; j < 3; j++)
                g_z[(row0 + r)*E3 + j*256 + col] = acc[r][j] + P[r*3 + j][col];
    }
}

// ---------------- windowed attention v8: WPB=16 + shift-dedup ------------
__global__ __launch_bounds__(ATHREADS, 2) void k_attn(const float* __restrict__ inb) {
    extern __shared__ unsigned char smraw[];
    __nv_bfloat16* Gm = (__nv_bfloat16*)smraw;           // [144][146] bf16
    uint32_t* Zq = (uint32_t*)(smraw + OFF_PZ);          // [144][36] bf16x2
    uint32_t* Zk = (uint32_t*)(smraw + OFF_ZK);          // [144][36]
    __nv_bfloat16* Pm = (__nv_bfloat16*)(smraw + OFF_PZ); // P [144][144] (Zq/Zk dead)
    uint32_t* Zv = (uint32_t*)smraw;                     // aliases Gm (dead after pass B)
    float* Fs   = (float*)(smraw + OFF_F);
    float* Us   = Fs + F_US;
    float* invA = Fs + F_INVA;
    float* Hn   = Fs + F_HN;
    float* bqS  = Fs + F_BQ;
    float* bkS  = Fs + F_BK;
    float* c0S  = Fs + F_C0;
    uint32_t* Hn2e = (uint32_t*)(Fs + F_HN2E);
    uint32_t* Hn2o = (uint32_t*)(Fs + F_HN2O);
    __nv_bfloat16* Wvb = (__nv_bfloat16*)(Fs + F_WVB);
    uint32_t* HP2E = (uint32_t*)(Fs + F_HP2E);
    uint32_t* HP2O = (uint32_t*)(Fs + F_HP2O);

    int tid = threadIdx.x;
    int bx = blockIdx.x, h = blockIdx.y;
    int v, g;
    if (bx < 64) { v = 0; g = bx; }
    else { int i = bx - 64; v = 1; g = (i < 8) ? i : i + 52; }
    bool dual = (v == 0) && (g >= 4) && (g < 56);
    int l0 = g * WPB;

    if (tid < 132)
        Hn[tid] = (tid < 128)
            ? 0.5f*(1.f - cosf(6.283185307179586f*(float)tid/127.f)) : 0.f;
    if (tid >= 192 && tid < 256) bqS[tid-192] = inb[h*64 + (tid-192)];
    if (tid >= 256 && tid < 320) bkS[tid-256] = inb[CC + h*64 + (tid-256)];

    // load Zq / Zk (row 143 zero-padded)
    for (int i = tid; i < RBP*32; i += ATHREADS) {
        int r = i >> 5, jw = i & 31;
        int tp = l0 + r;
        float2 aq = make_float2(0.f, 0.f), ak = make_float2(0.f, 0.f);
        if (r < 143 && tp >= PADN && tp < PADN + TT) {
            int src = v ? ((tp - PADN - SHIFTN + TT) & (TT-1)) : (tp - PADN);
            const float* zp = &g_z[src*E3 + h*64 + 2*jw];
            aq = *(const float2*)zp;
            ak = *(const float2*)(zp + CC);
        }
        Zq[r*ZST + jw] = f2b2(aq.x, aq.y);
        Zk[r*ZST + jw] = f2b2(ak.x, ak.y);
    }
    __syncthreads();

    // ---- G (HFMA2, LDS.128, rows strided by 36 -> conflict-free) ----
    for (int idx = tid; idx < 36*36; idx += ATHREADS) {
        int ta = idx / 36, tb = idx - ta*36;
        __nv_bfloat162 acc2[4][4];
        __nv_bfloat162 z2 = __float2bfloat162_rn(0.f);
#pragma unroll
        for (int i = 0; i < 4; i++)
#pragma unroll
            for (int i2 = 0; i2 < 4; i2++) acc2[i][i2] = z2;
        for (int jw = 0; jw < 32; jw += 4) {
            uint4 A[4], B[4];
#pragma unroll
            for (int i = 0; i < 4; i++) {
                A[i] = *(const uint4*)&Zq[(ta + 36*i)*ZST + jw];
                B[i] = *(const uint4*)&Zk[(tb + 36*i)*ZST + jw];
            }
#pragma unroll
            for (int i = 0; i < 4; i++)
#pragma unroll
                for (int i2 = 0; i2 < 4; i2++) {
                    acc2[i][i2] = __hfma2(u2b(A[i].x), u2b(B[i2].x), acc2[i][i2]);
                    acc2[i][i2] = __hfma2(u2b(A[i].y), u2b(B[i2].y), acc2[i][i2]);
                    acc2[i][i2] = __hfma2(u2b(A[i].z), u2b(B[i2].z), acc2[i][i2]);
                    acc2[i][i2] = __hfma2(u2b(A[i].w), u2b(B[i2].w), acc2[i][i2]);
                }
        }
#pragma unroll
        for (int i = 0; i < 4; i++)
#pragma unroll
            for (int i2 = 0; i2 < 4; i2++) {
                float gf = SCC*(__low2float(acc2[i][i2]) + __high2float(acc2[i][i2]));
                Gm[(ta + 36*i)*GST + tb + 36*i2] = __float2bfloat16_rn(gf);
            }
    }
#define HPF(i) (((i) >= 16 && (i) < 144) ? Hn[(i)-16] : 0.f)
    if (tid < 144) {
        float su = 0.f;
        for (int jw = 0; jw < 32; jw++) {
            float2 q2 = b2f(Zq[tid*ZST + jw]);
            su += q2.x*bkS[2*jw] + q2.y*bkS[2*jw+1];
        }
        Us[tid] = SCC*su;
    } else if (tid < 288) {
        int r = tid - 144;
        float sw = 0.f;
        for (int jw = 0; jw < 32; jw++) {
            float2 k2 = b2f(Zk[r*ZST + jw]);
            sw += k2.x*bqS[2*jw] + k2.y*bqS[2*jw+1];
        }
        Wvb[r] = __float2bfloat16_rn(SCC*sw);
    } else if (tid == 288) {
        float c0 = 0.f;
        for (int j = 0; j < 64; j++) c0 += bqS[j]*bkS[j];
        c0S[0] = SCC*c0;
    } else if (tid >= 320 && tid < 384) {
        int j = tid - 320;
        Hn2e[j] = f2b2(Hn[2*j], Hn[2*j+1]);
    } else if (tid >= 384 && tid < 448) {
        int j = tid - 384;
        Hn2o[j] = f2b2(Hn[2*j+1], Hn[2*j+2]);
    } else if (tid >= 448) {
        for (int j = tid - 448; j < 80; j += 64) {
            HP2E[j] = f2b2(HPF(2*j), HPF(2*j+1));
            HP2O[j] = f2b2(HPF(2*j+1), HPF(2*j+2));
        }
    }
    __syncthreads();

    // ---- pass A: softmax denominators (16 windows x 128 q) ----
    float c0 = c0S[0];
    for (int rr = tid; rr < 2048; rr += ATHREADS) {
        int dl = rr >> 7, q = rr & 127;
        if (l0 + dl >= LW) continue;
        int a = dl + q;
        float hq = Hn[q];
        float base = fmaf(hq, Us[a], c0);
        __nv_bfloat162 hq2 = __float2bfloat162_rn(hq);
        __nv_bfloat162 base2 = __float2bfloat162_rn(base);
        int odd = dl & 1;
        int e0 = dl + odd;
        const uint32_t* gp = (const uint32_t*)(Gm + a*GST + e0);
        const uint32_t* wp = (const uint32_t*)Wvb + (e0 >> 1);
        const uint32_t* hp = odd ? Hn2o : Hn2e;
        int npairs = 64 - odd;
        float sum = odd ? 2.f*exp2f(base) : 0.f;
#pragma unroll 4
        for (int j = 0; j < npairs; j++) {
            __nv_bfloat162 s2 = __hfma2(
                __hfma2(hq2, u2b(gp[j]), u2b(wp[j])), u2b(hp[j]), base2);
            float2 sf = __bfloat1622float2(s2);
            sum += exp2f(sf.x) + exp2f(sf.y);
        }
        invA[dl*128 + q] = 1.f/sum;
    }
    __syncthreads();

    // ---- pass B: P[a][b] into Pm (over dead Zq/Zk), 2 sub-batches of 8 dl ----
    // Same thread owns same (a,b2) in both sub-batches -> no sync between them.
    for (int s = 0; s < 2; s++) {
        int dbase = 8*s;
        for (int a = tid >> 2; a < 144; a += 128) {
            uint32_t gq2[8], base2[8];
            float iv[8];
            float ua = Us[a];
#pragma unroll
            for (int d = 0; d < 8; d++) {
                int dl = dbase + d;
                int qd = a - dl;
                bool va = (qd >= 0 && qd < 128);
                float hq = va ? Hn[qd] : 0.f;
                float bs = fmaf(hq, ua, c0);
                gq2[d] = f2b2(hq, hq);
                base2[d] = f2b2(bs, bs);
                iv[d] = (va && (l0 + dl) < LW) ? invA[dl*128 + qd] : 0.f;
            }
            int q4 = tid & 3;
            for (int jj = 0; jj < 18; jj++) {
                int b2 = 2*q4 + 8*jj;
                uint32_t gval2 = *(const uint32_t*)&Gm[a*GST + b2];
                uint32_t wb2 = ((const uint32_t*)Wvb)[b2 >> 1];
                float p0 = 0.f, p1 = 0.f;
#pragma unroll
                for (int d = 0; d < 8; d++) {
                    int dl = dbase + d;
                    uint32_t hk2u = (dl & 1)
                        ? HP2O[(b2 - dl + 15) >> 1]
                        : HP2E[(b2 - dl + 16) >> 1];
                    __nv_bfloat162 s2 = __hfma2(
                        __hfma2(u2b(gq2[d]), u2b(gval2), u2b(wb2)),
                        u2b(hk2u), u2b(base2[d]));
                    float2 sf = __bfloat1622float2(s2);
                    float2 hk = b2f(hk2u);
                    p0 = fmaf(hk.x*iv[d], exp2f(sf.x), p0);
                    p1 = fmaf(hk.y*iv[d], exp2f(sf.y), p1);
                }
                uint32_t* pp = (uint32_t*)&Pm[a*PST + b2];
                if (s) {
                    float2 old = b2f(*pp);
                    p0 += old.x; p1 += old.y;
                }
                *pp = f2b2(p0, p1);
            }
        }
    }
    __syncthreads();

    // ---- load Zv into dead G region ----
    for (int i = tid; i < RBP*32; i += ATHREADS) {
        int r = i >> 5, jw = i & 31;
        int tp = l0 + r;
        float2 av = make_float2(0.f, 0.f);
        if (r < 143 && tp >= PADN && tp < PADN + TT) {
            int src = v ? ((tp - PADN - SHIFTN + TT) & (TT-1)) : (tp - PADN);
            av = *(const float2*)&g_z[src*E3 + 2*CC + h*64 + 2*jw];
        }
        Zv[r*ZST + jw] = f2b2(av.x, av.y);
    }
    __syncthreads();

    // ---- PV (HFMA2 + f32 flush, LDS.128 V loads) ----
    for (int idx = tid; idx < 72*8; idx += ATHREADS) {
        int ta = idx >> 3, tj = idx & 7;
        int a0 = ta*2, j0 = tj*8;
        float2 accf[2][4];
#pragma unroll
        for (int i = 0; i < 2; i++)
#pragma unroll
            for (int c = 0; c < 4; c++) accf[i][c] = make_float2(0.f, 0.f);
        __nv_bfloat162 z2 = __float2bfloat162_rn(0.f);
        for (int cb = 0; cb < 72; cb += 8) {
            __nv_bfloat162 acc2[2][4];
#pragma unroll
            for (int i = 0; i < 2; i++)
#pragma unroll
                for (int c = 0; c < 4; c++) acc2[i][c] = z2;
            for (int bw = cb; bw < cb + 8; bw++) {
                uint4 V0 = *(const uint4*)&Zv[(2*bw)*ZST + (j0 >> 1)];
                uint4 V1 = *(const uint4*)&Zv[(2*bw+1)*ZST + (j0 >> 1)];
#pragma unroll
                for (int i = 0; i < 2; i++) {
                    __nv_bfloat162 pp = u2b(*(const uint32_t*)&Pm[(a0+i)*PST + 2*bw]);
                    __nv_bfloat162 pl = __low2bfloat162(pp);
                    __nv_bfloat162 ph = __high2bfloat162(pp);
                    acc2[i][0] = __hfma2(pl, u2b(V0.x), acc2[i][0]);
                    acc2[i][1] = __hfma2(pl, u2b(V0.y), acc2[i][1]);
                    acc2[i][2] = __hfma2(pl, u2b(V0.z), acc2[i][2]);
                    acc2[i][3] = __hfma2(pl, u2b(V0.w), acc2[i][3]);
                    acc2[i][0] = __hfma2(ph, u2b(V1.x), acc2[i][0]);
                    acc2[i][1] = __hfma2(ph, u2b(V1.y), acc2[i][1]);
                    acc2[i][2] = __hfma2(ph, u2b(V1.z), acc2[i][2]);
                    acc2[i][3] = __hfma2(ph, u2b(V1.w), acc2[i][3]);
                }
            }
#pragma unroll
            for (int i = 0; i < 2; i++)
#pragma unroll
                for (int c = 0; c < 4; c++) {
                    float2 f = __bfloat1622float2(acc2[i][c]);
                    accf[i][c].x += f.x;
                    accf[i][c].y += f.y;
                }
        }
#pragma unroll
        for (int i = 0; i < 2; i++) {
            int tp = l0 + a0 + i;
            if (tp < TPP) {
                float* dst = &g_acc[((size_t)v*TPP + tp)*CC + h*64 + j0];
#pragma unroll
                for (int c = 0; c < 4; c++) {
                    atomicAdd(&dst[2*c],   accf[i][c].x);
                    atomicAdd(&dst[2*c+1], accf[i][c].y);
                }
                if (dual) {
                    float* dst2 = &g_acc[((size_t)TPP + tp + SHIFTN)*CC + h*64 + j0];
#pragma unroll
                    for (int c = 0; c < 4; c++) {
                        atomicAdd(&dst2[2*c],   accf[i][c].x);
                        atomicAdd(&dst2[2*c+1], accf[i][c].y);
                    }
                }
            }
        }
    }
}

// ---------------- finalize (R9: 256 blocks, split-c 512, two GEMMs) ------
__global__ __launch_bounds__(512) void k_finalize(const float* __restrict__ inb,
                                                  const float* __restrict__ ob,
                                                  const float* __restrict__ pb) {
    __shared__ float U[4][CC];
    __shared__ float Y2[4][CC];
    __shared__ float P[4][CC];
    __shared__ float bb[4];
    int tid = threadIdx.x, half = tid >> 8, col = tid & 255;
    int t0 = blockIdx.x * 4;

    for (int idx = tid; idx < 4*CC; idx += 512) {
        int r = idx >> 8, c = idx & 255;
        float bvv = inb[2*CC + c];
        int t = t0 + r;
        float cm = cntf(t);
        float am = g_acc[(size_t)(t + PADN)*CC + c];
        float pm = (am + cm*bvv) / (cm + 1e-6f);
        int tau = (t + SHIFTN) & (TT-1);
        float cs = cntf(tau);
        float as = g_acc[(size_t)TPP*CC + (size_t)(tau + PADN)*CC + c];
        float ps = (as + cs*bvv) / (cs + 1e-6f);
        U[r][c] = 0.5f*(pm + ps);
    }
    if (tid < 4) {
        int t = t0 + tid;
        float cm = cntf(t);
        float cs = cntf((t + SHIFTN) & (TT-1));
        bb[tid] = 0.5f*(cm/(cm + 1e-6f) + cs/(cs + 1e-6f));
    }
    __syncthreads();

    float acc[4];
    int cbase = half * 128;
#pragma unroll
    for (int r = 0; r < 4; r++) acc[r] = 0.f;
    for (int cc = 0; cc < 128; cc++) {
        int c = cbase + cc;
        float w = g_wto[c*CC + col];
#pragma unroll
        for (int r = 0; r < 4; r++) acc[r] += U[r][c]*w;
    }
    if (half) {
#pragma unroll
        for (int r = 0; r < 4; r++) P[r][col] = acc[r];
    }
    __syncthreads();
    if (!half) {
        float obv = ob[col];
#pragma unroll
        for (int r = 0; r < 4; r++)
            Y2[r][col] = acc[r] + P[r][col] + bb[r]*obv;
    }
    __syncthreads();

#pragma unroll
    for (int r = 0; r < 4; r++) acc[r] = 0.f;
    for (int cc = 0; cc < 128; cc++) {
        int c = cbase + cc;
        float w = g_wtp[c*CC + col];
#pragma unroll
        for (int r = 0; r < 4; r++) acc[r] += Y2[r][c]*w;
    }
    if (half) {
#pragma unroll
        for (int r = 0; r < 4; r++) P[r][col] = acc[r];
    }
    __syncthreads();
    if (!half) {
        float pbv = pb[col];
        float colpart = 0.f;
#pragma unroll
        for (int r = 0; r < 4; r++) {
            float yp = acc[r] + P[r][col] + pbv;
            g_y[(size_t)(t0 + r)*CC + col] = yp;
            colpart += yp;
        }
        atomicAdd(&g_colsum[col], colpart);
    }
}

// ---------------- SE gate ----------------
__global__ __launch_bounds__(256) void k_se(const float* __restrict__ w1,
                                            const float* __restrict__ w2) {
    __shared__ float s[CC], s1[16];
    int tid = threadIdx.x;
    s[tid] = g_colsum[tid] * (1.f/(float)TT);
    __syncthreads();
    if (tid < 16) {
        float a = 0.f;
        for (int c = 0; c < CC; c++) a += s[c]*w1[tid*CC + c];
        s1[tid] = fmaxf(a, 0.f);
    }
    __syncthreads();
    float a = 0.f;
#pragma unroll
    for (int j = 0; j < 16; j++) a += s1[j]*w2[tid*16 + j];
    g_segate[tid] = 1.f/(1.f + __expf(-a));
}

// ---------------- residual + gate ----------------
__global__ void k_out(const float* __restrict__ x, float* __restrict__ out) {
    int i = blockIdx.x*256 + threadIdx.x;
    out[i] = x[i] + g_y[i]*g_segate[i & 255];
}

extern "C" void kernel_launch(void* const* d_in, const int* in_sizes, int n_in,
                              void* d_out, int out_size) {
    const float* x  = (const float*)d_in[0];
    const float* lg = (const float*)d_in[1];
    const float* lb = (const float*)d_in[2];
    const float* wi = (const float*)d_in[3];
    const float* ib = (const float*)d_in[4];
    const float* wo = (const float*)d_in[5];
    const float* ob = (const float*)d_in[6];
    const float* wp = (const float*)d_in[7];
    const float* pb = (const float*)d_in[8];
    const float* w1 = (const float*)d_in[9];
    const float* w2 = (const float*)d_in[10];
    float* out = (float*)d_out;

    cudaFuncSetAttribute(k_attn, cudaFuncAttributeMaxDynamicSharedMemorySize,
                         SMEM_BYTES);

    k_init<<<2300, 256>>>(wi, wo, wp);
    k_ln_z<<<256, 512>>>(x, lg, lb);
    k_attn<<<dim3(76, 4), ATHREADS, SMEM_BYTES>>>(ib);
    k_finalize<<<256, 512>>>(ib, ob, pb);
    k_se<<<1, 256>>>(w1, w2);
    k_out<<<1024, 256>>>(x, out);
}

// round 13
// speedup vs baseline: 1.3818x; 1.0187x over previous
#include <cuda_runtime.h>
#include <cuda_bf16.h>
#include <cstdint>
#include <stdint.h>

#define TT    1024
#define CC    256
#define E3    768
#define WINN  128
#define PADN  63
#define TPP   1150
#define LW    1023
#define SHIFTN 64
#define WPB   16
#define RBP   144
#define GST   146
#define ZST   36
#define PST   144
#define ATHREADS 512

// smem layout (bytes)
#define OFF_PZ  42048
#define OFF_ZK  62784
#define OFF_F   83520
#define SMEM_BYTES 94784

// Fs-region offsets (float slots)
#define F_US    0
#define F_INVA  144
#define F_HN    2192
#define F_BQ    2324
#define F_BK    2388
#define F_C0    2452
#define F_HN2E  2456
#define F_HN2O  2520
#define F_WVB   2584
#define F_HP2E  2656
#define F_HP2O  2736

#define SCC 0.18033688011112042f

__device__ float g_z[TT*E3];
__device__ float g_acc[2*TPP*CC];
__device__ float g_wti[CC*E3];
__device__ float g_wto[CC*CC];
__device__ float g_wtp[CC*CC];
__device__ float g_y[TT*CC];
__device__ float g_colsum[CC];
__device__ float g_segate[CC];

__device__ __forceinline__ float2 b2f(uint32_t u) {
    float2 r;
    r.x = __uint_as_float(u << 16);
    r.y = __uint_as_float(u & 0xffff0000u);
    return r;
}
__device__ __forceinline__ uint32_t f2b2(float a, float b) {
    __nv_bfloat162 t = __floats2bfloat162_rn(a, b);
    return *(uint32_t*)&t;
}
__device__ __forceinline__ float b2f1(__nv_bfloat16 h) {
    return __uint_as_float(((uint32_t)*(unsigned short*)&h) << 16);
}
__device__ __forceinline__ __nv_bfloat162 u2b(uint32_t u) {
    return *(__nv_bfloat162*)&u;
}

__device__ __forceinline__ float cntf(int t) {
    int tp = t + PADN;
    int lmin = tp - 127; if (lmin < 0) lmin = 0;
    int lmax = tp;       if (lmax > 1022) lmax = 1022;
    return (float)(lmax - lmin + 1);
}

// ---------------- init ----------------
__global__ void k_init(const float* __restrict__ wi,
                       const float* __restrict__ wo,
                       const float* __restrict__ wp) {
    int i = blockIdx.x * 256 + threadIdx.x;
    if (i < 2*TPP*CC) g_acc[i] = 0.f;
    if (i < CC) g_colsum[i] = 0.f;
    if (i < E3*CC) {
        int e = i >> 8, c = i & 255;
        g_wti[c*E3 + e] = wi[i];
    }
    if (i < CC*CC) {
        int e = i >> 8, c = i & 255;
        g_wto[c*CC + e] = wo[i];
        g_wtp[c*CC + e] = wp[i];
    }
}

// ---------------- LayerNorm + z (explicit 4x3 weight-load batching) ------
__global__ __launch_bounds__(512) void k_ln_z(const float* __restrict__ x,
                                              const float* __restrict__ lg,
                                              const float* __restrict__ lb) {
    __shared__ float Y[4][CC];
    __shared__ float sA[4][8], sB[4][8];
    __shared__ float P[12][CC];
    int tid = threadIdx.x, half = tid >> 8, col = tid & 255;
    int warp = tid >> 5, lane = tid & 31;
    int w8 = warp & 7;
    int row0 = blockIdx.x * 4;

    float gv = lg[col], bv = lb[col];
    float xv[2];
#pragma unroll
    for (int r2 = 0; r2 < 2; r2++) {
        int r = 2*half + r2;
        float v = x[(row0 + r)*CC + col];
        xv[r2] = v;
        float s = v, s2 = v*v;
#pragma unroll
        for (int o = 16; o; o >>= 1) {
            s  += __shfl_xor_sync(0xffffffffu, s, o);
            s2 += __shfl_xor_sync(0xffffffffu, s2, o);
        }
        if (lane == 0) { sA[r][w8] = s; sB[r][w8] = s2; }
    }
    __syncthreads();
#pragma unroll
    for (int r2 = 0; r2 < 2; r2++) {
        int r = 2*half + r2;
        float s = 0.f, s2 = 0.f;
#pragma unroll
        for (int w2 = 0; w2 < 8; w2++) { s += sA[r][w2]; s2 += sB[r][w2]; }
        float mu  = s * (1.f/CC);
        float var = s2 * (1.f/CC) - mu*mu;
        float rstd = rsqrtf(var + 1e-5f);
        Y[r][col] = (xv[r2] - mu) * rstd * gv + bv;
    }
    __syncthreads();

    float acc[4][3];
#pragma unroll
    for (int r = 0; r < 4; r++)
#pragma unroll
        for (int j = 0; j < 3; j++) acc[r][j] = 0.f;

    int cbase = half * 128;
    for (int cc = 0; cc < 128; cc += 4) {
        float wv[4][3];
#pragma unroll
        for (int u = 0; u < 4; u++)
#pragma unroll
            for (int j = 0; j < 3; j++)
                wv[u][j] = g_wti[(cbase + cc + u)*E3 + j*256 + col];
#pragma unroll
        for (int u = 0; u < 4; u++) {
            int c = cbase + cc + u;
            float y4[4];
#pragma unroll
            for (int r = 0; r < 4; r++) y4[r] = Y[r][c];
#pragma unroll
            for (int j = 0; j < 3; j++)
#pragma unroll
                for (int r = 0; r < 4; r++) acc[r][j] += y4[r]*wv[u][j];
        }
    }
    if (half) {
#pragma unroll
        for (int r = 0; r < 4; r++)
#pragma unroll
            for (int j = 0; j < 3; j++) P[r*3 + j][col] = acc[r][j];
    }
    __syncthreads();
    if (!half) {
#pragma unroll
        for (int r = 0; r < 4; r++)
#pragma unroll
            for (int j = 0; j < 3; j++)
                g_z[(row0 + r)*E3 + j*256 + col] = acc[r][j] + P[r*3 + j][col];
    }
}

// ---------------- windowed attention v8 (unchanged from R12) -------------
__global__ __launch_bounds__(ATHREADS, 2) void k_attn(const float* __restrict__ inb) {
    extern __shared__ unsigned char smraw[];
    __nv_bfloat16* Gm = (__nv_bfloat16*)smraw;
    uint32_t* Zq = (uint32_t*)(smraw + OFF_PZ);
    uint32_t* Zk = (uint32_t*)(smraw + OFF_ZK);
    __nv_bfloat16* Pm = (__nv_bfloat16*)(smraw + OFF_PZ);
    uint32_t* Zv = (uint32_t*)smraw;
    float* Fs   = (float*)(smraw + OFF_F);
    float* Us   = Fs + F_US;
    float* invA = Fs + F_INVA;
    float* Hn   = Fs + F_HN;
    float* bqS  = Fs + F_BQ;
    float* bkS  = Fs + F_BK;
    float* c0S  = Fs + F_C0;
    uint32_t* Hn2e = (uint32_t*)(Fs + F_HN2E);
    uint32_t* Hn2o = (uint32_t*)(Fs + F_HN2O);
    __nv_bfloat16* Wvb = (__nv_bfloat16*)(Fs + F_WVB);
    uint32_t* HP2E = (uint32_t*)(Fs + F_HP2E);
    uint32_t* HP2O = (uint32_t*)(Fs + F_HP2O);

    int tid = threadIdx.x;
    int bx = blockIdx.x, h = blockIdx.y;
    int v, g;
    if (bx < 64) { v = 0; g = bx; }
    else { int i = bx - 64; v = 1; g = (i < 8) ? i : i + 52; }
    bool dual = (v == 0) && (g >= 4) && (g < 56);
    int l0 = g * WPB;

    if (tid < 132)
        Hn[tid] = (tid < 128)
            ? 0.5f*(1.f - cosf(6.283185307179586f*(float)tid/127.f)) : 0.f;
    if (tid >= 192 && tid < 256) bqS[tid-192] = inb[h*64 + (tid-192)];
    if (tid >= 256 && tid < 320) bkS[tid-256] = inb[CC + h*64 + (tid-256)];

    for (int i = tid; i < RBP*32; i += ATHREADS) {
        int r = i >> 5, jw = i & 31;
        int tp = l0 + r;
        float2 aq = make_float2(0.f, 0.f), ak = make_float2(0.f, 0.f);
        if (r < 143 && tp >= PADN && tp < PADN + TT) {
            int src = v ? ((tp - PADN - SHIFTN + TT) & (TT-1)) : (tp - PADN);
            const float* zp = &g_z[src*E3 + h*64 + 2*jw];
            aq = *(const float2*)zp;
            ak = *(const float2*)(zp + CC);
        }
        Zq[r*ZST + jw] = f2b2(aq.x, aq.y);
        Zk[r*ZST + jw] = f2b2(ak.x, ak.y);
    }
    __syncthreads();

    for (int idx = tid; idx < 36*36; idx += ATHREADS) {
        int ta = idx / 36, tb = idx - ta*36;
        __nv_bfloat162 acc2[4][4];
        __nv_bfloat162 z2 = __float2bfloat162_rn(0.f);
#pragma unroll
        for (int i = 0; i < 4; i++)
#pragma unroll
            for (int i2 = 0; i2 < 4; i2++) acc2[i][i2] = z2;
        for (int jw = 0; jw < 32; jw += 4) {
            uint4 A[4], B[4];
#pragma unroll
            for (int i = 0; i < 4; i++) {
                A[i] = *(const uint4*)&Zq[(ta + 36*i)*ZST + jw];
                B[i] = *(const uint4*)&Zk[(tb + 36*i)*ZST + jw];
            }
#pragma unroll
            for (int i = 0; i < 4; i++)
#pragma unroll
                for (int i2 = 0; i2 < 4; i2++) {
                    acc2[i][i2] = __hfma2(u2b(A[i].x), u2b(B[i2].x), acc2[i][i2]);
                    acc2[i][i2] = __hfma2(u2b(A[i].y), u2b(B[i2].y), acc2[i][i2]);
                    acc2[i][i2] = __hfma2(u2b(A[i].z), u2b(B[i2].z), acc2[i][i2]);
                    acc2[i][i2] = __hfma2(u2b(A[i].w), u2b(B[i2].w), acc2[i][i2]);
                }
        }
#pragma unroll
        for (int i = 0; i < 4; i++)
#pragma unroll
            for (int i2 = 0; i2 < 4; i2++) {
                float gf = SCC*(__low2float(acc2[i][i2]) + __high2float(acc2[i][i2]));
                Gm[(ta + 36*i)*GST + tb + 36*i2] = __float2bfloat16_rn(gf);
            }
    }
#define HPF(i) (((i) >= 16 && (i) < 144) ? Hn[(i)-16] : 0.f)
    if (tid < 144) {
        float su = 0.f;
        for (int jw = 0; jw < 32; jw++) {
            float2 q2 = b2f(Zq[tid*ZST + jw]);
            su += q2.x*bkS[2*jw] + q2.y*bkS[2*jw+1];
        }
        Us[tid] = SCC*su;
    } else if (tid < 288) {
        int r = tid - 144;
        float sw = 0.f;
        for (int jw = 0; jw < 32; jw++) {
            float2 k2 = b2f(Zk[r*ZST + jw]);
            sw += k2.x*bqS[2*jw] + k2.y*bqS[2*jw+1];
        }
        Wvb[r] = __float2bfloat16_rn(SCC*sw);
    } else if (tid == 288) {
        float c0 = 0.f;
        for (int j = 0; j < 64; j++) c0 += bqS[j]*bkS[j];
        c0S[0] = SCC*c0;
    } else if (tid >= 320 && tid < 384) {
        int j = tid - 320;
        Hn2e[j] = f2b2(Hn[2*j], Hn[2*j+1]);
    } else if (tid >= 384 && tid < 448) {
        int j = tid - 384;
        Hn2o[j] = f2b2(Hn[2*j+1], Hn[2*j+2]);
    } else if (tid >= 448) {
        for (int j = tid - 448; j < 80; j += 64) {
            HP2E[j] = f2b2(HPF(2*j), HPF(2*j+1));
            HP2O[j] = f2b2(HPF(2*j+1), HPF(2*j+2));
        }
    }
    __syncthreads();

    float c0 = c0S[0];
    for (int rr = tid; rr < 2048; rr += ATHREADS) {
        int dl = rr >> 7, q = rr & 127;
        if (l0 + dl >= LW) continue;
        int a = dl + q;
        float hq = Hn[q];
        float base = fmaf(hq, Us[a], c0);
        __nv_bfloat162 hq2 = __float2bfloat162_rn(hq);
        __nv_bfloat162 base2 = __float2bfloat162_rn(base);
        int odd = dl & 1;
        int e0 = dl + odd;
        const uint32_t* gp = (const uint32_t*)(Gm + a*GST + e0);
        const uint32_t* wp = (const uint32_t*)Wvb + (e0 >> 1);
        const uint32_t* hp = odd ? Hn2o : Hn2e;
        int npairs = 64 - odd;
        float sum = odd ? 2.f*exp2f(base) : 0.f;
#pragma unroll 4
        for (int j = 0; j < npairs; j++) {
            __nv_bfloat162 s2 = __hfma2(
                __hfma2(hq2, u2b(gp[j]), u2b(wp[j])), u2b(hp[j]), base2);
            float2 sf = __bfloat1622float2(s2);
            sum += exp2f(sf.x) + exp2f(sf.y);
        }
        invA[dl*128 + q] = 1.f/sum;
    }
    __syncthreads();

    for (int s = 0; s < 2; s++) {
        int dbase = 8*s;
        for (int a = tid >> 2; a < 144; a += 128) {
            uint32_t gq2[8], base2[8];
            float iv[8];
            float ua = Us[a];
#pragma unroll
            for (int d = 0; d < 8; d++) {
                int dl = dbase + d;
                int qd = a - dl;
                bool va = (qd >= 0 && qd < 128);
                float hq = va ? Hn[qd] : 0.f;
                float bs = fmaf(hq, ua, c0);
                gq2[d] = f2b2(hq, hq);
                base2[d] = f2b2(bs, bs);
                iv[d] = (va && (l0 + dl) < LW) ? invA[dl*128 + qd] : 0.f;
            }
            int q4 = tid & 3;
            for (int jj = 0; jj < 18; jj++) {
                int b2 = 2*q4 + 8*jj;
                uint32_t gval2 = *(const uint32_t*)&Gm[a*GST + b2];
                uint32_t wb2 = ((const uint32_t*)Wvb)[b2 >> 1];
                float p0 = 0.f, p1 = 0.f;
#pragma unroll
                for (int d = 0; d < 8; d++) {
                    int dl = dbase + d;
                    uint32_t hk2u = (dl & 1)
                        ? HP2O[(b2 - dl + 15) >> 1]
                        : HP2E[(b2 - dl + 16) >> 1];
                    __nv_bfloat162 s2 = __hfma2(
                        __hfma2(u2b(gq2[d]), u2b(gval2), u2b(wb2)),
                        u2b(hk2u), u2b(base2[d]));
                    float2 sf = __bfloat1622float2(s2);
                    float2 hk = b2f(hk2u);
                    p0 = fmaf(hk.x*iv[d], exp2f(sf.x), p0);
                    p1 = fmaf(hk.y*iv[d], exp2f(sf.y), p1);
                }
                uint32_t* pp = (uint32_t*)&Pm[a*PST + b2];
                if (s) {
                    float2 old = b2f(*pp);
                    p0 += old.x; p1 += old.y;
                }
                *pp = f2b2(p0, p1);
            }
        }
    }
    __syncthreads();

    for (int i = tid; i < RBP*32; i += ATHREADS) {
        int r = i >> 5, jw = i & 31;
        int tp = l0 + r;
        float2 av = make_float2(0.f, 0.f);
        if (r < 143 && tp >= PADN && tp < PADN + TT) {
            int src = v ? ((tp - PADN - SHIFTN + TT) & (TT-1)) : (tp - PADN);
            av = *(const float2*)&g_z[src*E3 + 2*CC + h*64 + 2*jw];
        }
        Zv[r*ZST + jw] = f2b2(av.x, av.y);
    }
    __syncthreads();

    for (int idx = tid; idx < 72*8; idx += ATHREADS) {
        int ta = idx >> 3, tj = idx & 7;
        int a0 = ta*2, j0 = tj*8;
        float2 accf[2][4];
#pragma unroll
        for (int i = 0; i < 2; i++)
#pragma unroll
            for (int c = 0; c < 4; c++) accf[i][c] = make_float2(0.f, 0.f);
        __nv_bfloat162 z2 = __float2bfloat162_rn(0.f);
        for (int cb = 0; cb < 72; cb += 8) {
            __nv_bfloat162 acc2[2][4];
#pragma unroll
            for (int i = 0; i < 2; i++)
#pragma unroll
                for (int c = 0; c < 4; c++) acc2[i][c] = z2;
            for (int bw = cb; bw < cb + 8; bw++) {
                uint4 V0 = *(const uint4*)&Zv[(2*bw)*ZST + (j0 >> 1)];
                uint4 V1 = *(const uint4*)&Zv[(2*bw+1)*ZST + (j0 >> 1)];
#pragma unroll
                for (int i = 0; i < 2; i++) {
                    __nv_bfloat162 pp = u2b(*(const uint32_t*)&Pm[(a0+i)*PST + 2*bw]);
                    __nv_bfloat162 pl = __low2bfloat162(pp);
                    __nv_bfloat162 ph = __high2bfloat162(pp);
                    acc2[i][0] = __hfma2(pl, u2b(V0.x), acc2[i][0]);
                    acc2[i][1] = __hfma2(pl, u2b(V0.y), acc2[i][1]);
                    acc2[i][2] = __hfma2(pl, u2b(V0.z), acc2[i][2]);
                    acc2[i][3] = __hfma2(pl, u2b(V0.w), acc2[i][3]);
                    acc2[i][0] = __hfma2(ph, u2b(V1.x), acc2[i][0]);
                    acc2[i][1] = __hfma2(ph, u2b(V1.y), acc2[i][1]);
                    acc2[i][2] = __hfma2(ph, u2b(V1.z), acc2[i][2]);
                    acc2[i][3] = __hfma2(ph, u2b(V1.w), acc2[i][3]);
                }
            }
#pragma unroll
            for (int i = 0; i < 2; i++)
#pragma unroll
                for (int c = 0; c < 4; c++) {
                    float2 f = __bfloat1622float2(acc2[i][c]);
                    accf[i][c].x += f.x;
                    accf[i][c].y += f.y;
                }
        }
#pragma unroll
        for (int i = 0; i < 2; i++) {
            int tp = l0 + a0 + i;
            if (tp < TPP) {
                float* dst = &g_acc[((size_t)v*TPP + tp)*CC + h*64 + j0];
#pragma unroll
                for (int c = 0; c < 4; c++) {
                    atomicAdd(&dst[2*c],   accf[i][c].x);
                    atomicAdd(&dst[2*c+1], accf[i][c].y);
                }
                if (dual) {
                    float* dst2 = &g_acc[((size_t)TPP + tp + SHIFTN)*CC + h*64 + j0];
#pragma unroll
                    for (int c = 0; c < 4; c++) {
                        atomicAdd(&dst2[2*c],   accf[i][c].x);
                        atomicAdd(&dst2[2*c+1], accf[i][c].y);
                    }
                }
            }
        }
    }
}

// ---------------- finalize: explicit 8-wide weight-load batching ---------
__global__ __launch_bounds__(512) void k_finalize(const float* __restrict__ inb,
                                                  const float* __restrict__ ob,
                                                  const float* __restrict__ pb) {
    __shared__ float U[4][CC];
    __shared__ float Y2[4][CC];
    __shared__ float P[4][CC];
    __shared__ float bb[4];
    int tid = threadIdx.x, half = tid >> 8, col = tid & 255;
    int t0 = blockIdx.x * 4;

    for (int idx = tid; idx < 4*CC; idx += 512) {
        int r = idx >> 8, c = idx & 255;
        float bvv = inb[2*CC + c];
        int t = t0 + r;
        float cm = cntf(t);
        float am = g_acc[(size_t)(t + PADN)*CC + c];
        float pm = (am + cm*bvv) / (cm + 1e-6f);
        int tau = (t + SHIFTN) & (TT-1);
        float cs = cntf(tau);
        float as = g_acc[(size_t)TPP*CC + (size_t)(tau + PADN)*CC + c];
        float ps = (as + cs*bvv) / (cs + 1e-6f);
        U[r][c] = 0.5f*(pm + ps);
    }
    if (tid < 4) {
        int t = t0 + tid;
        float cm = cntf(t);
        float cs = cntf((t + SHIFTN) & (TT-1));
        bb[tid] = 0.5f*(cm/(cm + 1e-6f) + cs/(cs + 1e-6f));
    }
    __syncthreads();

    float acc[4];
    int cbase = half * 128;
#pragma unroll
    for (int r = 0; r < 4; r++) acc[r] = 0.f;
    for (int cc = 0; cc < 128; cc += 8) {
        float w[8];
#pragma unroll
        for (int u = 0; u < 8; u++)
            w[u] = g_wto[(cbase + cc + u)*CC + col];
#pragma unroll
        for (int u = 0; u < 8; u++) {
            int c = cbase + cc + u;
#pragma unroll
            for (int r = 0; r < 4; r++) acc[r] += U[r][c]*w[u];
        }
    }
    if (half) {
#pragma unroll
        for (int r = 0; r < 4; r++) P[r][col] = acc[r];
    }
    __syncthreads();
    if (!half) {
        float obv = ob[col];
#pragma unroll
        for (int r = 0; r < 4; r++)
            Y2[r][col] = acc[r] + P[r][col] + bb[r]*obv;
    }
    __syncthreads();

#pragma unroll
    for (int r = 0; r < 4; r++) acc[r] = 0.f;
    for (int cc = 0; cc < 128; cc += 8) {
        float w[8];
#pragma unroll
        for (int u = 0; u < 8; u++)
            w[u] = g_wtp[(cbase + cc + u)*CC + col];
#pragma unroll
        for (int u = 0; u < 8; u++) {
            int c = cbase + cc + u;
#pragma unroll
            for (int r = 0; r < 4; r++) acc[r] += Y2[r][c]*w[u];
        }
    }
    if (half) {
#pragma unroll
        for (int r = 0; r < 4; r++) P[r][col] = acc[r];
    }
    __syncthreads();
    if (!half) {
        float pbv = pb[col];
        float colpart = 0.f;
#pragma unroll
        for (int r = 0; r < 4; r++) {
            float yp = acc[r] + P[r][col] + pbv;
            g_y[(size_t)(t0 + r)*CC + col] = yp;
            colpart += yp;
        }
        atomicAdd(&g_colsum[col], colpart);
    }
}

// ---------------- SE gate ----------------
__global__ __launch_bounds__(256) void k_se(const float* __restrict__ w1,
                                            const float* __restrict__ w2) {
    __shared__ float s[CC], s1[16];
    int tid = threadIdx.x;
    s[tid] = g_colsum[tid] * (1.f/(float)TT);
    __syncthreads();
    if (tid < 16) {
        float a = 0.f;
        for (int c = 0; c < CC; c++) a += s[c]*w1[tid*CC + c];
        s1[tid] = fmaxf(a, 0.f);
    }
    __syncthreads();
    float a = 0.f;
#pragma unroll
    for (int j = 0; j < 16; j++) a += s1[j]*w2[tid*16 + j];
    g_segate[tid] = 1.f/(1.f + __expf(-a));
}

// ---------------- residual + gate ----------------
__global__ void k_out(const float* __restrict__ x, float* __restrict__ out) {
    int i = blockIdx.x*256 + threadIdx.x;
    out[i] = x[i] + g_y[i]*g_segate[i & 255];
}

extern "C" void kernel_launch(void* const* d_in, const int* in_sizes, int n_in,
                              void* d_out, int out_size) {
    const float* x  = (const float*)d_in[0];
    const float* lg = (const float*)d_in[1];
    const float* lb = (const float*)d_in[2];
    const float* wi = (const float*)d_in[3];
    const float* ib = (const float*)d_in[4];
    const float* wo = (const float*)d_in[5];
    const float* ob = (const float*)d_in[6];
    const float* wp = (const float*)d_in[7];
    const float* pb = (const float*)d_in[8];
    const float* w1 = (const float*)d_in[9];
    const float* w2 = (const float*)d_in[10];
    float* out = (float*)d_out;

    cudaFuncSetAttribute(k_attn, cudaFuncAttributeMaxDynamicSharedMemorySize,
                         SMEM_BYTES);

    k_init<<<2300, 256>>>(wi, wo, wp);
    k_ln_z<<<256, 512>>>(x, lg, lb);
    k_attn<<<dim3(76, 4), ATHREADS, SMEM_BYTES>>>(ib);
    k_finalize<<<256, 512>>>(ib, ob, pb);
    k_se<<<1, 256>>>(w1, w2);
    k_out<<<1024, 256>>>(x, out);
}